// round 12
// baseline (speedup 1.0000x reference)
#include <cuda_runtime.h>
#include <math.h>

#define S_    2048
#define HID_  2048
#define H_    16
#define D_    128
#define SCALE_F 0.08838834764831845f   // 1/sqrt(128)

typedef unsigned long long ull;

// packed f32x2 helpers (sm_103a)
#define FMA2(d, a, b) asm("fma.rn.f32x2 %0, %1, %2, %0;" : "+l"(d) : "l"(a), "l"(b))
#define MUL2(d, a, b) asm("mul.rn.f32x2 %0, %1, %2;" : "=l"(d) : "l"(a), "l"(b))
#define PACK2(d, x)   asm("mov.b64 %0, {%1, %1};" : "=l"(d) : "r"(__float_as_uint(x)))
#define UNPACK2(lo, hi, v) asm("mov.b64 {%0, %1}, %2;" : "=r"(lo), "=r"(hi) : "l"(v))

// ---------------- device scratch (no allocations allowed) ----------------
__device__ float g_q   [S_*HID_];   // q projection (= v), pre-rope
__device__ float g_qr  [S_*HID_];   // roped q
__device__ float g_kr  [S_*HID_];   // roped k
__device__ float g_comb[S_*HID_];   // g*mem + (1-g)*attn
__device__ float g_cos [S_*64];
__device__ float g_sin [S_*64];

// ---------------- RoPE tables (double precision, tiny) ----------------
__global__ void tables_k(const int* __restrict__ pos_ids)
{
    int s = blockIdx.x;
    int i = threadIdx.x;            // 0..63
    float inv = (float)exp(-(double)i * (log(10000.0) / 64.0));
    float ang = (float)pos_ids[s] * inv;
    double sd, cd;
    sincos((double)ang, &sd, &cd);
    g_cos[s*64 + i] = (float)cd;
    g_sin[s*64 + i] = (float)sd;
}

// ---------------- fp32 SGEMM via FFMA2, fused RoPE epilogue -------------------
// mode 1: grid (16,16,2). z=0: C=hs@Wq+bq -> writes g_q (pre-rope) + g_qr (roped)
//                        z=1: C=hs@Wk+bk -> writes g_kr (roped) only
// mode 0: grid (16,16,1). plain C = A@B (no bias), store to C.
// block 256, BM=BN=128, BK=8, 8x8 microtile, double-buffered smem
__global__ __launch_bounds__(256) void sgemm_k(const float* __restrict__ A,
                                               const float* __restrict__ Bq,
                                               const float* __restrict__ Bk,
                                               const float* __restrict__ biasq,
                                               const float* __restrict__ biask,
                                               float* __restrict__ C,
                                               int mode)
{
    __shared__ float As[2][8][132];    // transposed: As[buf][k][m]
    __shared__ float Bs[2][8][132];
    const int t  = threadIdx.x;
    const int ty = t >> 4, tx = t & 15;
    const int bx = blockIdx.x, by = blockIdx.y, bz = blockIdx.z;
    const float* B    = bz ? Bk    : Bq;
    const float* bias = bz ? biask : biasq;
    const int am = t >> 1,  ak = (t & 1)  << 2;
    const int bkr = t >> 5, bn = (t & 31) << 2;
    const float* Ap = A + (size_t)(by*128 + am) * HID_ + ak;
    const float* Bp = B + (size_t)bkr * HID_ + bx*128 + bn;

    ull acc2[8][4];
#pragma unroll
    for (int i = 0; i < 8; i++)
#pragma unroll
        for (int j = 0; j < 4; j++) acc2[i][j] = 0ull;

    float4 av = *(const float4*)(Ap);
    float4 bv = *(const float4*)(Bp);
    As[0][ak+0][am] = av.x; As[0][ak+1][am] = av.y;
    As[0][ak+2][am] = av.z; As[0][ak+3][am] = av.w;
    *(float4*)&Bs[0][bkr][bn] = bv;
    __syncthreads();

    int buf = 0;
    for (int k0 = 8; k0 < HID_; k0 += 8) {
        av = *(const float4*)(Ap + k0);
        bv = *(const float4*)(Bp + (size_t)k0 * HID_);
#pragma unroll
        for (int kk = 0; kk < 8; kk++) {
            float a[8];
            *(float4*)(a)     = *(const float4*)&As[buf][kk][ty*8];
            *(float4*)(a + 4) = *(const float4*)&As[buf][kk][ty*8 + 4];
            ull ap2[8];
#pragma unroll
            for (int i = 0; i < 8; i++) PACK2(ap2[i], a[i]);
            ulonglong2 b01 = *(const ulonglong2*)&Bs[buf][kk][tx*4];
            ulonglong2 b23 = *(const ulonglong2*)&Bs[buf][kk][64 + tx*4];
#pragma unroll
            for (int i = 0; i < 8; i++) {
                FMA2(acc2[i][0], ap2[i], b01.x);
                FMA2(acc2[i][1], ap2[i], b01.y);
                FMA2(acc2[i][2], ap2[i], b23.x);
                FMA2(acc2[i][3], ap2[i], b23.y);
            }
        }
        As[buf^1][ak+0][am] = av.x; As[buf^1][ak+1][am] = av.y;
        As[buf^1][ak+2][am] = av.z; As[buf^1][ak+3][am] = av.w;
        *(float4*)&Bs[buf^1][bkr][bn] = bv;
        __syncthreads();
        buf ^= 1;
    }
#pragma unroll
    for (int kk = 0; kk < 8; kk++) {
        float a[8];
        *(float4*)(a)     = *(const float4*)&As[buf][kk][ty*8];
        *(float4*)(a + 4) = *(const float4*)&As[buf][kk][ty*8 + 4];
        ull ap2[8];
#pragma unroll
        for (int i = 0; i < 8; i++) PACK2(ap2[i], a[i]);
        ulonglong2 b01 = *(const ulonglong2*)&Bs[buf][kk][tx*4];
        ulonglong2 b23 = *(const ulonglong2*)&Bs[buf][kk][64 + tx*4];
#pragma unroll
        for (int i = 0; i < 8; i++) {
            FMA2(acc2[i][0], ap2[i], b01.x);
            FMA2(acc2[i][1], ap2[i], b01.y);
            FMA2(acc2[i][2], ap2[i], b23.x);
            FMA2(acc2[i][3], ap2[i], b23.y);
        }
    }

    const int colA = bx*128 + tx*4;          // head bx, head-local j = tx*4 (<64)
    float4 bva = make_float4(0.f,0.f,0.f,0.f), bvb = bva;
    if (mode) {
        bva = *(const float4*)(bias + colA);
        bvb = *(const float4*)(bias + colA + 64);
    }
#pragma unroll
    for (int i = 0; i < 8; i++) {
        int row = by*128 + ty*8 + i;         // = s
        unsigned lo, hi;
        float c0[4], c1[4];
        UNPACK2(lo, hi, acc2[i][0]); c0[0] = __uint_as_float(lo); c0[1] = __uint_as_float(hi);
        UNPACK2(lo, hi, acc2[i][1]); c0[2] = __uint_as_float(lo); c0[3] = __uint_as_float(hi);
        UNPACK2(lo, hi, acc2[i][2]); c1[0] = __uint_as_float(lo); c1[1] = __uint_as_float(hi);
        UNPACK2(lo, hi, acc2[i][3]); c1[2] = __uint_as_float(lo); c1[3] = __uint_as_float(hi);
        float4 o1, o2;
        o1.x = c0[0] + bva.x; o1.y = c0[1] + bva.y;
        o1.z = c0[2] + bva.z; o1.w = c0[3] + bva.w;
        o2.x = c1[0] + bvb.x; o2.y = c1[1] + bvb.y;
        o2.z = c1[2] + bvb.z; o2.w = c1[3] + bvb.w;
        if (mode == 0) {
            *(float4*)&C[(size_t)row * HID_ + colA]      = o1;
            *(float4*)&C[(size_t)row * HID_ + colA + 64] = o2;
        } else {
            // fused RoPE: thread holds partner pair (j, j+64); cos/sin index = j
            float4 cs = *(const float4*)&g_cos[(size_t)row*64 + tx*4];
            float4 sn = *(const float4*)&g_sin[(size_t)row*64 + tx*4];
            float4 r1, r2;
            r1.x = o1.x*cs.x - o2.x*sn.x;  r2.x = o2.x*cs.x + o1.x*sn.x;
            r1.y = o1.y*cs.y - o2.y*sn.y;  r2.y = o2.y*cs.y + o1.y*sn.y;
            r1.z = o1.z*cs.z - o2.z*sn.z;  r2.z = o2.z*cs.z + o1.z*sn.z;
            r1.w = o1.w*cs.w - o2.w*sn.w;  r2.w = o2.w*cs.w + o1.w*sn.w;
            size_t off = (size_t)row * HID_ + colA;
            if (bz == 0) {
                *(float4*)&g_q [off]      = o1;     // v = pre-rope q
                *(float4*)&g_q [off + 64] = o2;
                *(float4*)&g_qr[off]      = r1;
                *(float4*)&g_qr[off + 64] = r2;
            } else {
                *(float4*)&g_kr[off]      = r1;
                *(float4*)&g_kr[off + 64] = r2;
            }
        }
    }
}

// ---------------- memory path output: g * (sq@M_h) / (sq.z_h + eps) ----------------
// grid (32 qblocks, 16 heads), block 256
__global__ __launch_bounds__(256) void memout_k(const float* __restrict__ M,
                                                const float* __restrict__ z,
                                                const float* __restrict__ beta)
{
    __shared__ float sqs[64][132];
    __shared__ float Ms[16][132];
    __shared__ float den[64];
    int qb = blockIdx.x, h = blockIdx.y;
    int t = threadIdx.x, ty = t >> 4, tx = t & 15;

    for (int it = t; it < 64*32; it += 256) {
        int r = it >> 5, c4 = (it & 31) << 2;
        float4 v = *(const float4*)&g_qr[(size_t)(qb*64 + r)*HID_ + h*128 + c4];
        float4 o;
        o.x = v.x > 0.f ? v.x + 1.f : __expf(v.x);
        o.y = v.y > 0.f ? v.y + 1.f : __expf(v.y);
        o.z = v.z > 0.f ? v.z + 1.f : __expf(v.z);
        o.w = v.w > 0.f ? v.w + 1.f : __expf(v.w);
        *(float4*)&sqs[r][c4] = o;
    }
    __syncthreads();
    if (t < 64) {
        float s = 0.f;
        const float* zh = z + h*128;
#pragma unroll 4
        for (int d = 0; d < 128; d++) s = fmaf(sqs[t][d], zh[d], s);
        den[t] = s;
    }

    float acc[4][8];
#pragma unroll
    for (int i = 0; i < 4; i++)
#pragma unroll
        for (int j = 0; j < 8; j++) acc[i][j] = 0.f;

    const float* Mh = M + h*128*128;
    for (int d0 = 0; d0 < 128; d0 += 16) {
        __syncthreads();
        for (int it = t; it < 16*32; it += 256) {
            int dd = it >> 5, e4 = (it & 31) << 2;
            *(float4*)&Ms[dd][e4] = *(const float4*)(Mh + (d0 + dd)*128 + e4);
        }
        __syncthreads();
#pragma unroll
        for (int dd = 0; dd < 16; dd++) {
            float a_[4], b_[8];
#pragma unroll
            for (int i = 0; i < 4; i++) a_[i] = sqs[ty*4 + i][d0 + dd];
#pragma unroll
            for (int j = 0; j < 8; j++) b_[j] = Ms[dd][j*16 + tx];
#pragma unroll
            for (int i = 0; i < 4; i++)
#pragma unroll
                for (int j = 0; j < 8; j++)
                    acc[i][j] = fmaf(a_[i], b_[j], acc[i][j]);
        }
    }
    __syncthreads();
    float g = 1.f / (1.f + __expf(-beta[0]));
#pragma unroll
    for (int i = 0; i < 4; i++) {
        float sc = g / (den[ty*4 + i] + 1e-8f);
#pragma unroll
        for (int j = 0; j < 8; j++)
            g_comb[(size_t)(qb*64 + ty*4 + i)*HID_ + h*128 + j*16 + tx] = acc[i][j] * sc;
    }
}

// ---------------- flash attention (fp32, causal, FFMA2), adds (1-g)*O into g_comb --
// register-resident online softmax with 16-lane shfl reductions
#define LDK_ 132
#define LDS_ 68
__global__ __launch_bounds__(256) void attn_k(const float* __restrict__ beta)
{
    extern __shared__ float sm[];
    float* Qs = sm;                  // 64*132
    float* Ks = Qs + 64*LDK_;
    float* Vs = Ks + 64*LDK_;
    float* Ss = Vs + 64*LDK_;        // 64*68 (probs)

    int qb = gridDim.x - 1 - blockIdx.x;   // heavy blocks first
    int h  = blockIdx.y;
    int t  = threadIdx.x, ty = t >> 4, tx = t & 15;

    for (int it = t; it < 64*32; it += 256) {
        int r = it >> 5, c4 = (it & 31) << 2;
        *(float4*)&Qs[r*LDK_ + c4] =
            *(const float4*)&g_qr[(size_t)(qb*64 + r)*HID_ + h*128 + c4];
    }

    float m_i[4], l_i[4];
    ull acc2[4][4];                  // output pairs: d = tx*8 + 2*c (+1)
#pragma unroll
    for (int i = 0; i < 4; i++) {
        m_i[i] = -1e30f; l_i[i] = 0.f;
#pragma unroll
        for (int c = 0; c < 4; c++) acc2[i][c] = 0ull;
    }
    __syncthreads();

    for (int kb = 0; kb <= qb; kb++) {
        for (int it = t; it < 64*32; it += 256) {
            int r = it >> 5, c4 = (it & 31) << 2;
            *(float4*)&Ks[r*LDK_ + c4] =
                *(const float4*)&g_kr[(size_t)(kb*64 + r)*HID_ + h*128 + c4];
            *(float4*)&Vs[r*LDK_ + c4] =
                *(const float4*)&g_q[(size_t)(kb*64 + r)*HID_ + h*128 + c4];  // v = q
        }
        __syncthreads();

        // S = Q @ K^T  via packed dot products (rows ty*4+i, cols j*16+tx)
        ull s2[4][4];
#pragma unroll
        for (int i = 0; i < 4; i++)
#pragma unroll
            for (int j = 0; j < 4; j++) s2[i][j] = 0ull;
#pragma unroll 2
        for (int d = 0; d < 128; d += 4) {
            ulonglong2 q2[4], k2[4];
#pragma unroll
            for (int i = 0; i < 4; i++) q2[i] = *(const ulonglong2*)&Qs[(ty*4 + i)*LDK_ + d];
#pragma unroll
            for (int j = 0; j < 4; j++) k2[j] = *(const ulonglong2*)&Ks[(j*16 + tx)*LDK_ + d];
#pragma unroll
            for (int i = 0; i < 4; i++)
#pragma unroll
                for (int j = 0; j < 4; j++) {
                    FMA2(s2[i][j], q2[i].x, k2[j].x);
                    FMA2(s2[i][j], q2[i].y, k2[j].y);
                }
        }
        float s[4][4];
#pragma unroll
        for (int i = 0; i < 4; i++)
#pragma unroll
            for (int j = 0; j < 4; j++) {
                unsigned lo, hi;
                UNPACK2(lo, hi, s2[i][j]);
                s[i][j] = (__uint_as_float(lo) + __uint_as_float(hi)) * SCALE_F;
            }
        if (kb == qb) {
#pragma unroll
            for (int i = 0; i < 4; i++)
#pragma unroll
                for (int j = 0; j < 4; j++)
                    if ((j*16 + tx) > (ty*4 + i)) s[i][j] = -1e30f;
        }

        // register-resident online softmax (16-lane butterfly per row)
        float al[4];
#pragma unroll
        for (int i = 0; i < 4; i++) {
            float mx = fmaxf(fmaxf(s[i][0], s[i][1]), fmaxf(s[i][2], s[i][3]));
            mx = fmaxf(mx, __shfl_xor_sync(0xffffffffu, mx, 1));
            mx = fmaxf(mx, __shfl_xor_sync(0xffffffffu, mx, 2));
            mx = fmaxf(mx, __shfl_xor_sync(0xffffffffu, mx, 4));
            mx = fmaxf(mx, __shfl_xor_sync(0xffffffffu, mx, 8));
            float mnew = fmaxf(m_i[i], mx);
            al[i] = __expf(m_i[i] - mnew);
            float sum = 0.f;
#pragma unroll
            for (int j = 0; j < 4; j++) {
                float p = __expf(s[i][j] - mnew);
                s[i][j] = p;
                sum += p;
            }
            sum += __shfl_xor_sync(0xffffffffu, sum, 1);
            sum += __shfl_xor_sync(0xffffffffu, sum, 2);
            sum += __shfl_xor_sync(0xffffffffu, sum, 4);
            sum += __shfl_xor_sync(0xffffffffu, sum, 8);
            l_i[i] = l_i[i]*al[i] + sum;
            m_i[i] = mnew;
        }
#pragma unroll
        for (int i = 0; i < 4; i++) {
#pragma unroll
            for (int j = 0; j < 4; j++)
                Ss[(ty*4 + i)*LDS_ + j*16 + tx] = s[i][j];
            ull al2;
            PACK2(al2, al[i]);
#pragma unroll
            for (int c = 0; c < 4; c++) MUL2(acc2[i][c], acc2[i][c], al2);
        }
        __syncthreads();

        // O += P @ V  (packed along contiguous d: thread covers d = tx*8..tx*8+7)
        for (int j0 = 0; j0 < 64; j0 += 4) {
            float4 p4[4];
#pragma unroll
            for (int i = 0; i < 4; i++) p4[i] = *(const float4*)&Ss[(ty*4 + i)*LDS_ + j0];
#pragma unroll
            for (int u = 0; u < 4; u++) {
                ull pp[4];
#pragma unroll
                for (int i = 0; i < 4; i++) {
                    float pv = (u==0)?p4[i].x:(u==1)?p4[i].y:(u==2)?p4[i].z:p4[i].w;
                    PACK2(pp[i], pv);
                }
                ulonglong2 vA = *(const ulonglong2*)&Vs[(j0 + u)*LDK_ + tx*8];
                ulonglong2 vB = *(const ulonglong2*)&Vs[(j0 + u)*LDK_ + tx*8 + 4];
#pragma unroll
                for (int i = 0; i < 4; i++) {
                    FMA2(acc2[i][0], pp[i], vA.x);
                    FMA2(acc2[i][1], pp[i], vA.y);
                    FMA2(acc2[i][2], pp[i], vB.x);
                    FMA2(acc2[i][3], pp[i], vB.y);
                }
            }
        }
        __syncthreads();
    }

    float g  = 1.f / (1.f + __expf(-beta[0]));
    float w1 = 1.f - g;
#pragma unroll
    for (int i = 0; i < 4; i++) {
        float sc = w1 / l_i[i];
        float* base = g_comb + (size_t)(qb*64 + ty*4 + i)*HID_ + h*128 + tx*8;
#pragma unroll
        for (int c = 0; c < 4; c++) {
            unsigned lo, hi;
            UNPACK2(lo, hi, acc2[i][c]);
            float2 cur = *(float2*)(base + 2*c);
            cur.x += __uint_as_float(lo) * sc;
            cur.y += __uint_as_float(hi) * sc;
            *(float2*)(base + 2*c) = cur;
        }
    }
}

// ---------------- M_new / z_new init ----------------
__global__ void minit_k(const float* __restrict__ M, const float* __restrict__ z,
                        float* __restrict__ outM, float* __restrict__ outZ)
{
    int i = blockIdx.x*256 + threadIdx.x;
    if (i < H_*D_*D_) outM[i] = M[i];
    if (i < H_*D_)    outZ[i] = z[i];
}

// ---------------- M_new += sk^T @ v ; z_new += sum_s sk (split-S atomics) ----------------
// grid (16 heads, 16 s-chunks), block 256
__global__ __launch_bounds__(256) void macc_k(float* __restrict__ outM,
                                              float* __restrict__ outZ)
{
    __shared__ float sks[8][132];
    __shared__ float vs[8][132];
    int h = blockIdx.x, ch = blockIdx.y;
    int t = threadIdx.x, ty = t >> 4, tx = t & 15;
    int sr = t >> 5, d4 = (t & 31) << 2;

    float acc[8][8];
#pragma unroll
    for (int i = 0; i < 8; i++)
#pragma unroll
        for (int j = 0; j < 8; j++) acc[i][j] = 0.f;
    float zpart = 0.f;

    int base = ch*128;
    for (int s0 = 0; s0 < 128; s0 += 8) {
        int srow = base + s0 + sr;
        float4 kv = *(const float4*)&g_kr[(size_t)srow*HID_ + h*128 + d4];
        float4 o;
        o.x = kv.x > 0.f ? kv.x + 1.f : __expf(kv.x);
        o.y = kv.y > 0.f ? kv.y + 1.f : __expf(kv.y);
        o.z = kv.z > 0.f ? kv.z + 1.f : __expf(kv.z);
        o.w = kv.w > 0.f ? kv.w + 1.f : __expf(kv.w);
        *(float4*)&sks[sr][d4] = o;
        *(float4*)&vs[sr][d4]  = *(const float4*)&g_q[(size_t)srow*HID_ + h*128 + d4];
        __syncthreads();
#pragma unroll
        for (int ss = 0; ss < 8; ss++) {
            float a_[8], b_[8];
#pragma unroll
            for (int i = 0; i < 8; i++) a_[i] = sks[ss][ty*8 + i];
#pragma unroll
            for (int j = 0; j < 8; j++) b_[j] = vs[ss][j*16 + tx];
#pragma unroll
            for (int i = 0; i < 8; i++)
#pragma unroll
                for (int j = 0; j < 8; j++)
                    acc[i][j] = fmaf(a_[i], b_[j], acc[i][j]);
        }
        if (t < 128) {
#pragma unroll
            for (int ss = 0; ss < 8; ss++) zpart += sks[ss][t];
        }
        __syncthreads();
    }
    float* out = outM + h*(128*128);
#pragma unroll
    for (int i = 0; i < 8; i++)
#pragma unroll
        for (int j = 0; j < 8; j++)
            atomicAdd(&out[(ty*8 + i)*128 + j*16 + tx], acc[i][j]);
    if (t < 128) atomicAdd(&outZ[h*128 + t], zpart);
}

// ---------------- launch ----------------
extern "C" void kernel_launch(void* const* d_in, const int* in_sizes, int n_in,
                              void* d_out, int out_size)
{
    const float* hs   = (const float*)d_in[0];
    const int*   pos  = (const int*)  d_in[2];
    const float* Wq   = (const float*)d_in[3];
    const float* bq   = (const float*)d_in[4];
    const float* Wk   = (const float*)d_in[5];
    const float* bk   = (const float*)d_in[6];
    const float* Wo   = (const float*)d_in[7];
    const float* beta = (const float*)d_in[8];
    const float* M    = (const float*)d_in[9];
    const float* z    = (const float*)d_in[10];

    float* out  = (float*)d_out;
    float* outF = out;                        // (1,2048,2048)
    float* outM = out + (size_t)S_*HID_;      // (16,128,128)
    float* outZ = outM + H_*D_*D_;            // (16,128)

    float *pcomb;
    cudaGetSymbolAddress((void**)&pcomb, g_comb);

    const int ATTN_SMEM = (3*64*LDK_ + 64*LDS_) * (int)sizeof(float);   // 118784
    cudaFuncSetAttribute(attn_k, cudaFuncAttributeMaxDynamicSharedMemorySize, ATTN_SMEM);

    tables_k<<<S_, 64>>>(pos);
    // fused Q+K projection (+bias, +RoPE) in one launch
    sgemm_k<<<dim3(16, 16, 2), 256>>>(hs, Wq, Wk, bq, bk, nullptr, 1);
    memout_k<<<dim3(32, 16), 256>>>(M, z, beta);           // g_comb = g*mem
    attn_k<<<dim3(32, 16), 256, ATTN_SMEM>>>(beta);        // g_comb += (1-g)*attn
    minit_k<<<(H_*D_*D_)/256, 256>>>(M, z, outM, outZ);
    macc_k<<<dim3(16, 16), 256>>>(outM, outZ);
    // final output projection (no bias)
    sgemm_k<<<dim3(16, 16, 1), 256>>>(pcomb, Wo, Wo, nullptr, nullptr, outF, 0);
}